// round 6
// baseline (speedup 1.0000x reference)
#include <cuda_runtime.h>
#include <math.h>
#include <cstdint>

// Problem constants
#define BB 2
#define SS 2048
#define EE 1024
#define HH 16
#define HD 64
#define BH (BB*HH)
#define SCALE 0.125f   // 1/sqrt(64)

#define ST 68    // smem row stride (words) for permuted operand tiles

// Scratch (allocation-free rule: __device__ globals)
static __device__ float g_q  [(size_t)BH*SS*64];   // (bh, s, d)        fp32
static __device__ float g_kp [(size_t)BH*SS*64];   // (bh, s, pk(d))    tf32-rounded
static __device__ float g_vp [(size_t)BH*64*SS];   // (bh, v, tilePerm(s)) tf32-rounded
static __device__ float g_attp[(size_t)BB*SS*EE];  // (b, s, h*64+pk(c)) tf32-rounded
static __device__ float g_wop[(size_t)EE*EE];      // (e_out, blk64perm(e_in)) tf32-rounded

// ---------------------------------------------------------------------------
// helpers
// ---------------------------------------------------------------------------
__device__ __forceinline__ uint32_t f2tf32(float x) {
    uint32_t r;
    asm("cvt.rna.tf32.f32 %0, %1;" : "=r"(r) : "f"(x));
    return r;
}
__device__ __forceinline__ float frna(float x) { return __uint_as_float(f2tf32(x)); }
__device__ __forceinline__ int pk64(int k) { return (k & 3)*16 + (k >> 2); }

// D(16x8) += A(16x8) * B(8x8)
__device__ __forceinline__ void mma_tf32(float c[4], float a0, float a1,
                                         float a2, float a3, float b0, float b1) {
    asm volatile(
        "mma.sync.aligned.m16n8k8.row.col.f32.tf32.tf32.f32 "
        "{%0,%1,%2,%3}, {%4,%5,%6,%7}, {%8,%9}, {%0,%1,%2,%3};"
        : "+f"(c[0]), "+f"(c[1]), "+f"(c[2]), "+f"(c[3])
        : "r"(__float_as_uint(a0)), "r"(__float_as_uint(a1)),
          "r"(__float_as_uint(a2)), "r"(__float_as_uint(a3)),
          "r"(__float_as_uint(b0)), "r"(__float_as_uint(b1)));
}

// ---------------------------------------------------------------------------
// Kernel 0: Wo pre-pass.  g_wop[n][blk64(k) + pk64(k%64)] = rna(Wo[k][n])
// Tile: k 64 x n 32, smem transpose, coalesced both sides.
// ---------------------------------------------------------------------------
__global__ __launch_bounds__(256) void wo_prep(const float* __restrict__ Wo)
{
    __shared__ float t[64][33];
    int k0 = blockIdx.x * 64, n0 = blockIdx.y * 32;
    int tx = threadIdx.x & 31, ty = threadIdx.x >> 5;

    for (int i = ty; i < 64; i += 8)
        t[i][tx] = Wo[(size_t)(k0 + i)*EE + n0 + tx];
    __syncthreads();
    for (int i = ty; i < 32; i += 8) {
        int x0 = tx, x1 = tx + 32;                 // output cols within 64-block
        g_wop[(size_t)(n0 + i)*EE + k0 + x0] = frna(t[4*(x0 & 15) + (x0 >> 4)][i]);
        g_wop[(size_t)(n0 + i)*EE + k0 + x1] = frna(t[4*(x1 & 15) + (x1 >> 4)][i]);
    }
}

// ---------------------------------------------------------------------------
// Kernel 1: QKV projection on tf32 mma.
// CTA = (bh, 128-row s tile), 256 threads = 8 warps x 16 rows.
// Outputs: Q natural fp32 | K permuted+rounded (s, pk(d)) |
//          V rounded, v-major with within-64-tile permuted s.
// ---------------------------------------------------------------------------
#define AST 68
#define BST 72
#define QKV_SMEM_FLOATS (128*AST + 3*64*BST)
#define QKV_SMEM_BYTES  (QKV_SMEM_FLOATS*4)

__global__ __launch_bounds__(256) void qkv_mma_kernel(
    const float* __restrict__ x,
    const float* __restrict__ Wq, const float* __restrict__ bq,
    const float* __restrict__ Wk, const float* __restrict__ bk,
    const float* __restrict__ Wv, const float* __restrict__ bv)
{
    extern __shared__ __align__(16) float smf[];
    float* At = smf;                 // [m=128][k=64] stride AST
    float* Ws = smf + 128*AST;       // 3 x [k=64][n=64] stride BST

    int tid  = threadIdx.x;
    int lane = tid & 31;
    int warp = tid >> 5;
    int g = lane >> 2, q = lane & 3;

    int bh = blockIdx.x; int b = bh >> 4, h = bh & 15;
    int s0 = blockIdx.y * 128;
    int wm = warp * 16;

    for (int idx = tid; idx < 2048; idx += 256) {
        int row = idx >> 4, c4 = (idx & 15) * 4;
        *(float4*)&At[row*AST + c4] = *(const float4*)&x[((size_t)b*SS + s0 + row)*EE + h*HD + c4];
    }
    const float* Wp[3] = {Wq, Wk, Wv};
    for (int w = 0; w < 3; ++w)
        for (int idx = tid; idx < 1024; idx += 256) {
            int row = idx >> 4, c4 = (idx & 15) * 4;
            *(float4*)&Ws[w*64*BST + row*BST + c4] = *(const float4*)&Wp[w][(size_t)row*64 + c4];
        }
    __syncthreads();

    int r0g = s0 + wm + g, r1g = s0 + wm + g + 8;
    int sr0 = (r0g & ~63) + pk64(r0g & 63);       // permuted s index for V
    int sr1 = (r1g & ~63) + pk64(r1g & 63);

    const float* bp[3] = {bq, bk, bv};
    for (int w = 0; w < 3; ++w) {
        float acc[8][4] = {};
        const float* B = &Ws[w*64*BST];
        #pragma unroll
        for (int kk = 0; kk < 8; ++kk) {
            float a0 = At[(wm + g    )*AST + kk*8 + q    ];
            float a1 = At[(wm + g + 8)*AST + kk*8 + q    ];
            float a2 = At[(wm + g    )*AST + kk*8 + q + 4];
            float a3 = At[(wm + g + 8)*AST + kk*8 + q + 4];
            a0 = frna(a0); a1 = frna(a1); a2 = frna(a2); a3 = frna(a3);
            #pragma unroll
            for (int nb = 0; nb < 8; ++nb) {
                float b0 = frna(B[(kk*8 + q    )*BST + nb*8 + g]);
                float b1 = frna(B[(kk*8 + q + 4)*BST + nb*8 + g]);
                mma_tf32(acc[nb], a0, a1, a2, a3, b0, b1);
            }
        }

        #pragma unroll
        for (int nb = 0; nb < 8; ++nb) {
            int c = nb*8 + 2*q;
            float bb0 = bp[w][c], bb1 = bp[w][c + 1];
            float v00 = acc[nb][0] + bb0, v01 = acc[nb][1] + bb1;
            float v10 = acc[nb][2] + bb0, v11 = acc[nb][3] + bb1;
            if (w == 0) {
                float* o = &g_q[((size_t)bh*SS)*64];
                o[(size_t)r0g*64 + c] = v00; o[(size_t)r0g*64 + c + 1] = v01;
                o[(size_t)r1g*64 + c] = v10; o[(size_t)r1g*64 + c + 1] = v11;
            } else if (w == 1) {
                int pc = pk64(c);                 // pk64(c+1) == pc+16 (c even)
                float* o = &g_kp[((size_t)bh*SS)*64];
                o[(size_t)r0g*64 + pc]      = frna(v00);
                o[(size_t)r0g*64 + pc + 16] = frna(v01);
                o[(size_t)r1g*64 + pc]      = frna(v10);
                o[(size_t)r1g*64 + pc + 16] = frna(v11);
            } else {
                float* o = &g_vp[(size_t)bh*64*SS];
                o[(size_t)c*SS + sr0]       = frna(v00);
                o[(size_t)(c + 1)*SS + sr0] = frna(v01);
                o[(size_t)c*SS + sr1]       = frna(v10);
                o[(size_t)(c + 1)*SS + sr1] = frna(v11);
            }
        }
    }
}

// ---------------------------------------------------------------------------
// Kernel 2: attention.  CTA = (bh, 128 q-rows), 256 threads = 8 warps.
// All operands pre-permuted + pre-rounded; inner loop = LDS.128 + HMMA + exp.
// QK 1x, PV 1x (rna).  No-max softmax; one divide at the end.
// ---------------------------------------------------------------------------
#define ATTN_SMEM_FLOATS (2*64*ST + 8*16*ST)
#define ATTN_SMEM_BYTES  (ATTN_SMEM_FLOATS*4)

__global__ __launch_bounds__(256, 2) void attn_mma_kernel(const float* __restrict__ mask)
{
    extern __shared__ __align__(16) float smf[];
    float* Kp = smf;                    // [n=s_loc][pk(d)]
    float* Vp = smf + 64*ST;            // [n=v][pk(s_loc)]
    float* Pp = smf + 2*64*ST + (threadIdx.x >> 5)*(16*ST);   // [m][pk(s_loc)]

    int tid = threadIdx.x;
    int lane = tid & 31;
    int warp = tid >> 5;
    int g = lane >> 2, q = lane & 3;

    int bh = blockIdx.x, b = bh >> 4, h = bh & 15;
    int q0 = blockIdx.y * 128;
    int wr = q0 + warp * 16;

    // Q fragments (SCALE folded, rna)
    float aq[8][4];
    {
        const float* qb = &g_q[((size_t)bh*SS + wr)*64];
        #pragma unroll
        for (int kk = 0; kk < 8; ++kk) {
            aq[kk][0] = frna(qb[(size_t)g      *64 + kk*8 + q    ] * SCALE);
            aq[kk][1] = frna(qb[(size_t)(g + 8)*64 + kk*8 + q    ] * SCALE);
            aq[kk][2] = frna(qb[(size_t)g      *64 + kk*8 + q + 4] * SCALE);
            aq[kk][3] = frna(qb[(size_t)(g + 8)*64 + kk*8 + q + 4] * SCALE);
        }
    }

    float oacc[8][4] = {};
    float lsum0 = 0.f, lsum1 = 0.f;
    const float* mrow0 = &mask[(size_t)(wr + g    )*SS];
    const float* mrow1 = &mask[(size_t)(wr + g + 8)*SS];
    int pc0 = 16*((2*q) & 3) + (q >> 1);   // pk col base for c = 8nb+2q (add 2nb)

    for (int jt = 0; jt < SS/64; ++jt) {
        int s0 = jt * 64;
        __syncthreads();
        for (int idx = tid; idx < 1024; idx += 256) {
            int row = idx >> 4, c4 = (idx & 15) * 4;
            *(float4*)&Kp[row*ST + c4] = *(const float4*)&g_kp[((size_t)bh*SS + s0 + row)*64 + c4];
            *(float4*)&Vp[row*ST + c4] = *(const float4*)&g_vp[((size_t)bh*64 + row)*SS + s0 + c4];
        }
        __syncthreads();

        // ---- S = Q K^T ----
        float sacc[8][4] = {};
        #pragma unroll
        for (int nb = 0; nb < 8; ++nb) {
            const float4* kr = (const float4*)&Kp[(8*nb + g)*ST + 16*q];
            float4 f0 = kr[0], f1 = kr[1], f2 = kr[2], f3 = kr[3];
            mma_tf32(sacc[nb], aq[0][0], aq[0][1], aq[0][2], aq[0][3], f0.x, f0.y);
            mma_tf32(sacc[nb], aq[1][0], aq[1][1], aq[1][2], aq[1][3], f0.z, f0.w);
            mma_tf32(sacc[nb], aq[2][0], aq[2][1], aq[2][2], aq[2][3], f1.x, f1.y);
            mma_tf32(sacc[nb], aq[3][0], aq[3][1], aq[3][2], aq[3][3], f1.z, f1.w);
            mma_tf32(sacc[nb], aq[4][0], aq[4][1], aq[4][2], aq[4][3], f2.x, f2.y);
            mma_tf32(sacc[nb], aq[5][0], aq[5][1], aq[5][2], aq[5][3], f2.z, f2.w);
            mma_tf32(sacc[nb], aq[6][0], aq[6][1], aq[6][2], aq[6][3], f3.x, f3.y);
            mma_tf32(sacc[nb], aq[7][0], aq[7][1], aq[7][2], aq[7][3], f3.z, f3.w);
        }

        // ---- P = exp(S * mask), store permuted+rounded; partial row sums ----
        float ps0 = 0.f, ps1 = 0.f;
        float2 m01 = __ldg((const float2*)&mrow0[s0 + 2*q]);
        float2 m23 = __ldg((const float2*)&mrow1[s0 + 2*q]);
        #pragma unroll
        for (int nb = 0; nb < 8; ++nb) {
            float2 n01 = m01, n23 = m23;
            if (nb < 7) {   // prefetch next
                m01 = __ldg((const float2*)&mrow0[s0 + 8*(nb + 1) + 2*q]);
                m23 = __ldg((const float2*)&mrow1[s0 + 8*(nb + 1) + 2*q]);
            }
            float p0 = frna(__expf(sacc[nb][0] * n01.x));
            float p1 = frna(__expf(sacc[nb][1] * n01.y));
            float p2 = frna(__expf(sacc[nb][2] * n23.x));
            float p3 = frna(__expf(sacc[nb][3] * n23.y));
            ps0 += p0 + p1; ps1 += p2 + p3;
            int pc = pc0 + 2*nb;
            Pp[g*ST + pc]            = p0;
            Pp[g*ST + pc + 16]       = p1;
            Pp[(g + 8)*ST + pc]      = p2;
            Pp[(g + 8)*ST + pc + 16] = p3;
        }
        ps0 += __shfl_xor_sync(0xffffffffu, ps0, 1);
        ps0 += __shfl_xor_sync(0xffffffffu, ps0, 2);
        ps1 += __shfl_xor_sync(0xffffffffu, ps1, 1);
        ps1 += __shfl_xor_sync(0xffffffffu, ps1, 2);
        lsum0 += ps0; lsum1 += ps1;
        __syncwarp();

        // ---- O += P V ----
        #pragma unroll
        for (int u = 0; u < 4; ++u) {
            float4 pa0 = *(const float4*)&Pp[g*ST       + 16*q + 4*u];
            float4 pa1 = *(const float4*)&Pp[(g + 8)*ST + 16*q + 4*u];
            #pragma unroll
            for (int nb = 0; nb < 8; ++nb) {
                float4 vb = *(const float4*)&Vp[(8*nb + g)*ST + 16*q + 4*u];
                mma_tf32(oacc[nb], pa0.x, pa1.x, pa0.y, pa1.y, vb.x, vb.y);
                mma_tf32(oacc[nb], pa0.z, pa1.z, pa0.w, pa1.w, vb.z, vb.w);
            }
        }
        __syncwarp();   // Pp reads done before next tile's epilogue rewrites
    }

    // normalize + write permuted+rounded to g_attp (b, s, h*64 + pk(c))
    float inv0 = 1.f / lsum0, inv1 = 1.f / lsum1;
    float* o0 = &g_attp[((size_t)b*SS + wr + g    )*EE + h*64];
    float* o1 = &g_attp[((size_t)b*SS + wr + g + 8)*EE + h*64];
    #pragma unroll
    for (int nb = 0; nb < 8; ++nb) {
        int pc = pc0 + 2*nb;
        o0[pc]      = frna(oacc[nb][0] * inv0);
        o0[pc + 16] = frna(oacc[nb][1] * inv0);
        o1[pc]      = frna(oacc[nb][2] * inv1);
        o1[pc + 16] = frna(oacc[nb][3] * inv1);
    }
}

// ---------------------------------------------------------------------------
// Kernel 3: output projection, 1x tf32 (all operands pre-rounded+permuted).
// out(4096x1024) = att @ Wo + bo.  CTA tile 128x64, K chunks of 64.
// ---------------------------------------------------------------------------
#define OUT_SMEM_FLOATS (128*ST + 64*ST)
#define OUT_SMEM_BYTES  (OUT_SMEM_FLOATS*4)

__global__ __launch_bounds__(256) void out_mma_kernel(
    const float* __restrict__ bo, float* __restrict__ out)
{
    extern __shared__ __align__(16) float smf[];
    float* As = smf;               // [m=128][pk(k)]
    float* Bs = smf + 128*ST;      // [n=64][pk(k)]

    int tid = threadIdx.x;
    int lane = tid & 31;
    int warp = tid >> 5;
    int g = lane >> 2, q = lane & 3;

    int e0 = blockIdx.x * 64;
    int r0 = blockIdx.y * 128;
    int wm = warp * 16;

    float oacc[8][4] = {};

    for (int kc = 0; kc < EE; kc += 64) {
        __syncthreads();
        for (int idx = tid; idx < 2048; idx += 256) {
            int row = idx >> 4, c4 = (idx & 15) * 4;
            *(float4*)&As[row*ST + c4] = *(const float4*)&g_attp[(size_t)(r0 + row)*EE + kc + c4];
        }
        for (int idx = tid; idx < 1024; idx += 256) {
            int row = idx >> 4, c4 = (idx & 15) * 4;
            *(float4*)&Bs[row*ST + c4] = *(const float4*)&g_wop[(size_t)(e0 + row)*EE + kc + c4];
        }
        __syncthreads();

        #pragma unroll
        for (int u = 0; u < 4; ++u) {
            float4 a0 = *(const float4*)&As[(wm + g    )*ST + 16*q + 4*u];
            float4 a1 = *(const float4*)&As[(wm + g + 8)*ST + 16*q + 4*u];
            #pragma unroll
            for (int nb = 0; nb < 8; ++nb) {
                float4 bb = *(const float4*)&Bs[(8*nb + g)*ST + 16*q + 4*u];
                mma_tf32(oacc[nb], a0.x, a1.x, a0.y, a1.y, bb.x, bb.y);
                mma_tf32(oacc[nb], a0.z, a1.z, a0.w, a1.w, bb.z, bb.w);
            }
        }
    }

    float* o0 = &out[(size_t)(r0 + wm + g    )*EE + e0];
    float* o1 = &out[(size_t)(r0 + wm + g + 8)*EE + e0];
    #pragma unroll
    for (int nb = 0; nb < 8; ++nb) {
        int c = nb*8 + 2*q;
        float bb0 = bo[e0 + c], bb1 = bo[e0 + c + 1];
        o0[c]     = oacc[nb][0] + bb0;
        o0[c + 1] = oacc[nb][1] + bb1;
        o1[c]     = oacc[nb][2] + bb0;
        o1[c + 1] = oacc[nb][3] + bb1;
    }
}

// ---------------------------------------------------------------------------
extern "C" void kernel_launch(void* const* d_in, const int* in_sizes, int n_in,
                              void* d_out, int out_size)
{
    const float* x    = (const float*)d_in[0];
    const float* mask = (const float*)d_in[1];
    const float* Wq   = (const float*)d_in[2];
    const float* bq   = (const float*)d_in[3];
    const float* Wk   = (const float*)d_in[4];
    const float* bk   = (const float*)d_in[5];
    const float* Wv   = (const float*)d_in[6];
    const float* bv   = (const float*)d_in[7];
    const float* Wo   = (const float*)d_in[8];
    const float* bo   = (const float*)d_in[9];
    float* out = (float*)d_out;

    cudaFuncSetAttribute(qkv_mma_kernel,  cudaFuncAttributeMaxDynamicSharedMemorySize, QKV_SMEM_BYTES);
    cudaFuncSetAttribute(attn_mma_kernel, cudaFuncAttributeMaxDynamicSharedMemorySize, ATTN_SMEM_BYTES);
    cudaFuncSetAttribute(out_mma_kernel,  cudaFuncAttributeMaxDynamicSharedMemorySize, OUT_SMEM_BYTES);

    wo_prep<<<dim3(EE/64, EE/32), 256>>>(Wo);
    qkv_mma_kernel<<<dim3(BH, SS/128), 256, QKV_SMEM_BYTES>>>(x, Wq, bq, Wk, bk, Wv, bv);
    attn_mma_kernel<<<dim3(BH, SS/128), 256, ATTN_SMEM_BYTES>>>(mask);
    out_mma_kernel<<<dim3(EE/64, (BB*SS)/128), 256, OUT_SMEM_BYTES>>>(bo, out);
}